// round 1
// baseline (speedup 1.0000x reference)
#include <cuda_runtime.h>
#include <cuda_bf16.h>
#include <math.h>

// Problem dims (fixed by the reference)
#define BB 8
#define MM 2048
#define DD 1024
#define HALF_D (DD / 2)
#define ROWS (BB * MM)          // 16384

// ---------------------------------------------------------------------------
// Scratch (device globals: allocation-free, graph-capture safe)
// ---------------------------------------------------------------------------
__device__ float g_Q[(size_t)ROWS * DD];
__device__ float g_K[(size_t)ROWS * DD];
__device__ float g_V[(size_t)ROWS * DD];
__device__ float g_S[(size_t)BB * MM * MM];
__device__ float g_cos[(size_t)MM * HALF_D];
__device__ float g_sin[(size_t)MM * HALF_D];

// ---------------------------------------------------------------------------
// RoPE tables: theta = 10000^(-2*(i-1)/D); ang = m * theta (fp32 chain like JAX)
// ---------------------------------------------------------------------------
__global__ void rope_tables_kernel() {
    int idx = blockIdx.x * blockDim.x + threadIdx.x;
    if (idx >= MM * HALF_D) return;
    int m = idx / HALF_D;
    int i = idx % HALF_D;
    // high-precision theta, then fp32 angle like the fp32 reference
    double theta_d = pow(10000.0, -2.0 * ((double)i - 1.0) / (double)DD);
    float theta = (float)theta_d;
    float ang = (float)m * theta;
    g_cos[idx] = cosf(ang);
    g_sin[idx] = sinf(ang);
}

// ---------------------------------------------------------------------------
// In-place RoPE rotation on a [ROWS, DD] tensor
// ---------------------------------------------------------------------------
__global__ void rope_apply_kernel(float* __restrict__ t) {
    long idx = (long)blockIdx.x * blockDim.x + threadIdx.x;   // pair index
    if (idx >= (long)ROWS * HALF_D) return;
    int col = (int)(idx % HALF_D);
    long row = idx / HALF_D;
    int m = (int)(row % MM);
    float2* p = reinterpret_cast<float2*>(t + row * DD) + col;
    float2 v = *p;
    float c = g_cos[(size_t)m * HALF_D + col];
    float s = g_sin[(size_t)m * HALF_D + col];
    float2 r;
    r.x = v.x * c + v.y * s;
    r.y = -v.x * s + v.y * c;
    *p = r;
}

// ---------------------------------------------------------------------------
// Row softmax over rows of length MM (2048): one CTA per row, regs-resident
// ---------------------------------------------------------------------------
__global__ void __launch_bounds__(256) softmax_kernel(float* __restrict__ S) {
    __shared__ float red[256];
    long row = blockIdx.x;
    float4* p = reinterpret_cast<float4*>(S + row * (long)MM);
    int t = threadIdx.x;
    float4 v0 = p[t];
    float4 v1 = p[t + 256];

    float mx = fmaxf(fmaxf(fmaxf(v0.x, v0.y), fmaxf(v0.z, v0.w)),
                     fmaxf(fmaxf(v1.x, v1.y), fmaxf(v1.z, v1.w)));
    red[t] = mx;
    __syncthreads();
    for (int s = 128; s > 0; s >>= 1) {
        if (t < s) red[t] = fmaxf(red[t], red[t + s]);
        __syncthreads();
    }
    mx = red[0];
    __syncthreads();

    v0.x = expf(v0.x - mx); v0.y = expf(v0.y - mx);
    v0.z = expf(v0.z - mx); v0.w = expf(v0.w - mx);
    v1.x = expf(v1.x - mx); v1.y = expf(v1.y - mx);
    v1.z = expf(v1.z - mx); v1.w = expf(v1.w - mx);

    float sum = (v0.x + v0.y + v0.z + v0.w) + (v1.x + v1.y + v1.z + v1.w);
    red[t] = sum;
    __syncthreads();
    for (int s = 128; s > 0; s >>= 1) {
        if (t < s) red[t] += red[t + s];
        __syncthreads();
    }
    float inv = 1.0f / red[0];

    v0.x *= inv; v0.y *= inv; v0.z *= inv; v0.w *= inv;
    v1.x *= inv; v1.y *= inv; v1.z *= inv; v1.w *= inv;
    p[t] = v0;
    p[t + 256] = v1;
}

// ---------------------------------------------------------------------------
// Tiled SGEMM, 128x128x8, 8x8 per thread.
//   C[m,n] = alpha * sum_k A[m,k] * Bop[k,n]
//   BT=true : B is [N,K] row-major (Bop = B^T), K-contiguous (NT gemm)
//   BT=false: B is [K,N] row-major, N-contiguous (NN gemm)
// All dims assumed divisible by tile sizes (true for this problem).
// ---------------------------------------------------------------------------
template <bool BT>
__global__ void __launch_bounds__(256) sgemm128_kernel(
    const float* __restrict__ A, const float* __restrict__ B,
    float* __restrict__ C, int N, int K,
    long sA, long sB, long sC, float alpha)
{
    constexpr int BM = 128, BN = 128, BK = 8, TM = 8, TN = 8;
    A += (long)blockIdx.z * sA;
    B += (long)blockIdx.z * sB;
    C += (long)blockIdx.z * sC;

    const int row0 = blockIdx.y * BM;
    const int col0 = blockIdx.x * BN;

    __shared__ float As[BK][BM];
    __shared__ float Bs[BK][BN];

    const int tid = threadIdx.x;
    const int tr = tid >> 4;          // 0..15
    const int tc = tid & 15;          // 0..15

    // A tile load: 128 rows x 8 k, 2 threads/row, one float4 each along K
    const int aRow = tid >> 1;
    const int aCol = (tid & 1) * 4;
    const float* Aptr = A + (long)(row0 + aRow) * K + aCol;

    // B tile load
    const float* Bptr;
    int bRow, bCol;
    if (BT) {
        bRow = tid >> 1;              // n within tile
        bCol = (tid & 1) * 4;         // k within tile
        Bptr = B + (long)(col0 + bRow) * K + bCol;
    } else {
        bRow = tid >> 5;              // k within tile (8 rows, 32 thr/row)
        bCol = (tid & 31) * 4;        // n within tile
        Bptr = B + (long)bRow * N + col0 + bCol;
    }

    float acc[TM][TN] = {};

    for (int k0 = 0; k0 < K; k0 += BK) {
        float4 av = *reinterpret_cast<const float4*>(Aptr + k0);
        As[aCol + 0][aRow] = av.x;
        As[aCol + 1][aRow] = av.y;
        As[aCol + 2][aRow] = av.z;
        As[aCol + 3][aRow] = av.w;
        if (BT) {
            float4 bv = *reinterpret_cast<const float4*>(Bptr + k0);
            Bs[bCol + 0][bRow] = bv.x;
            Bs[bCol + 1][bRow] = bv.y;
            Bs[bCol + 2][bRow] = bv.z;
            Bs[bCol + 3][bRow] = bv.w;
        } else {
            float4 bv = *reinterpret_cast<const float4*>(Bptr + (long)k0 * N);
            *reinterpret_cast<float4*>(&Bs[bRow][bCol]) = bv;
        }
        __syncthreads();

#pragma unroll
        for (int kk = 0; kk < BK; kk++) {
            float a[TM], b[TN];
            float4 a0 = *reinterpret_cast<const float4*>(&As[kk][tr * TM]);
            float4 a1 = *reinterpret_cast<const float4*>(&As[kk][tr * TM + 4]);
            float4 b0 = *reinterpret_cast<const float4*>(&Bs[kk][tc * TN]);
            float4 b1 = *reinterpret_cast<const float4*>(&Bs[kk][tc * TN + 4]);
            a[0] = a0.x; a[1] = a0.y; a[2] = a0.z; a[3] = a0.w;
            a[4] = a1.x; a[5] = a1.y; a[6] = a1.z; a[7] = a1.w;
            b[0] = b0.x; b[1] = b0.y; b[2] = b0.z; b[3] = b0.w;
            b[4] = b1.x; b[5] = b1.y; b[6] = b1.z; b[7] = b1.w;
#pragma unroll
            for (int i = 0; i < TM; i++)
#pragma unroll
                for (int j = 0; j < TN; j++)
                    acc[i][j] += a[i] * b[j];
        }
        __syncthreads();
    }

#pragma unroll
    for (int i = 0; i < TM; i++) {
        long r = (long)(row0 + tr * TM + i) * N + col0 + tc * TN;
        float4 c0, c1;
        c0.x = alpha * acc[i][0]; c0.y = alpha * acc[i][1];
        c0.z = alpha * acc[i][2]; c0.w = alpha * acc[i][3];
        c1.x = alpha * acc[i][4]; c1.y = alpha * acc[i][5];
        c1.z = alpha * acc[i][6]; c1.w = alpha * acc[i][7];
        *reinterpret_cast<float4*>(C + r)     = c0;
        *reinterpret_cast<float4*>(C + r + 4) = c1;
    }
}

// ---------------------------------------------------------------------------
// Launch
// ---------------------------------------------------------------------------
extern "C" void kernel_launch(void* const* d_in, const int* in_sizes, int n_in,
                              void* d_out, int out_size) {
    (void)in_sizes; (void)n_in; (void)out_size;
    const float* x  = (const float*)d_in[0];
    const float* wq = (const float*)d_in[1];
    const float* wk = (const float*)d_in[2];
    const float* wv = (const float*)d_in[3];
    float* out = (float*)d_out;

    float *Q, *K, *V, *S;
    cudaGetSymbolAddress((void**)&Q, g_Q);
    cudaGetSymbolAddress((void**)&K, g_K);
    cudaGetSymbolAddress((void**)&V, g_V);
    cudaGetSymbolAddress((void**)&S, g_S);

    // 1. RoPE tables
    rope_tables_kernel<<<(MM * HALF_D + 255) / 256, 256>>>();

    // 2. Projections: Q/K/V = x @ W^T   (NT gemm, M=16384, N=K=1024)
    dim3 gProj(DD / 128, ROWS / 128, 1);
    sgemm128_kernel<true><<<gProj, 256>>>(x, wq, Q, DD, DD, 0, 0, 0, 1.0f);
    sgemm128_kernel<true><<<gProj, 256>>>(x, wk, K, DD, DD, 0, 0, 0, 1.0f);
    sgemm128_kernel<true><<<gProj, 256>>>(x, wv, V, DD, DD, 0, 0, 0, 1.0f);

    // 3. RoPE on Q and K (in place)
    long pairs = (long)ROWS * HALF_D;
    rope_apply_kernel<<<(unsigned)((pairs + 255) / 256), 256>>>(Q);
    rope_apply_kernel<<<(unsigned)((pairs + 255) / 256), 256>>>(K);

    // 4. scores = Qr @ Kr^T * 1/sqrt(D)  (batched NT, M=N=2048, K=1024)
    dim3 gScore(MM / 128, MM / 128, BB);
    sgemm128_kernel<true><<<gScore, 256>>>(Q, K, S, MM, DD,
                                           (long)MM * DD, (long)MM * DD,
                                           (long)MM * MM, 0.03125f);

    // 5. softmax over rows
    softmax_kernel<<<BB * MM, 256>>>(S);

    // 6. out = attn @ V  (batched NN, M=2048, N=1024, K=2048)
    dim3 gOut(DD / 128, MM / 128, BB);
    sgemm128_kernel<false><<<gOut, 256>>>(S, V, out, DD, MM,
                                          (long)MM * MM, (long)MM * DD,
                                          (long)MM * DD, 1.0f);
}

// round 3
// speedup vs baseline: 2.6993x; 2.6993x over previous
#include <cuda_runtime.h>
#include <cuda_bf16.h>
#include <math.h>
#include <stdint.h>

// Problem dims (fixed)
#define BB 8
#define MM 2048
#define DD 1024
#define HALF_D 512
#define ROWS 16384           // BB*MM
#define K3P 3072             // 3*DD  (split-K for K=1024 GEMMs)
#define K3S 6144             // 3*MM  (split-K for PV GEMM, K=2048)

// ---------------------------------------------------------------------------
// Device-global scratch (allocation-free, graph-capture safe)
// ---------------------------------------------------------------------------
__device__ __nv_bfloat16 g_x3[(size_t)ROWS * K3P];     // x  split, A-side
__device__ __nv_bfloat16 g_w3q[(size_t)DD * K3P];      // wq split, B-side
__device__ __nv_bfloat16 g_w3k[(size_t)DD * K3P];
__device__ __nv_bfloat16 g_w3v[(size_t)DD * K3P];
__device__ float g_Qf[(size_t)ROWS * DD];
__device__ float g_Kf[(size_t)ROWS * DD];
__device__ float g_Vf[(size_t)ROWS * DD];
__device__ __nv_bfloat16 g_Q3[(size_t)ROWS * K3P];     // rotated Q split, A-side
__device__ __nv_bfloat16 g_K3[(size_t)ROWS * K3P];     // rotated K split, B-side
__device__ __nv_bfloat16 g_V3T[(size_t)BB * DD * K3S]; // V^T split, B-side
__device__ float g_Sf[(size_t)BB * MM * MM];           // scores fp32
__device__ __nv_bfloat16 g_S3[(size_t)BB * MM * K3S];  // attn split, A-side
__device__ float g_cos[(size_t)MM * HALF_D];
__device__ float g_sin[(size_t)MM * HALF_D];

// ---------------------------------------------------------------------------
// PTX helpers (base sm_80+-class ISA: mma.sync / ldmatrix / cp.async)
// ---------------------------------------------------------------------------
__device__ __forceinline__ uint32_t smem_u32(const void* p) {
    uint32_t a;
    asm("{ .reg .u64 t; cvta.to.shared.u64 t, %1; cvt.u32.u64 %0, t; }" : "=r"(a) : "l"(p));
    return a;
}
__device__ __forceinline__ void mma16816(float* d, const uint32_t* a, const uint32_t* b) {
    asm volatile(
        "mma.sync.aligned.m16n8k16.row.col.f32.bf16.bf16.f32 "
        "{%0,%1,%2,%3}, {%4,%5,%6,%7}, {%8,%9}, {%0,%1,%2,%3};"
        : "+f"(d[0]), "+f"(d[1]), "+f"(d[2]), "+f"(d[3])
        : "r"(a[0]), "r"(a[1]), "r"(a[2]), "r"(a[3]), "r"(b[0]), "r"(b[1]));
}
__device__ __forceinline__ void ldsm4(uint32_t* r, uint32_t addr) {
    asm volatile("ldmatrix.sync.aligned.m8n8.x4.shared.b16 {%0,%1,%2,%3}, [%4];"
                 : "=r"(r[0]), "=r"(r[1]), "=r"(r[2]), "=r"(r[3]) : "r"(addr));
}
__device__ __forceinline__ void cpasync16(uint32_t dst, const void* src) {
    asm volatile("cp.async.cg.shared.global [%0], [%1], 16;" :: "r"(dst), "l"(src));
}
__device__ __forceinline__ void cp_commit() {
    asm volatile("cp.async.commit_group;" ::: "memory");
}
template <int N>
__device__ __forceinline__ void cp_wait() {
    asm volatile("cp.async.wait_group %0;" :: "n"(N) : "memory");
}

// ---------------------------------------------------------------------------
// bf16 split helpers
// ---------------------------------------------------------------------------
__device__ __forceinline__ void split_bf16(float f, __nv_bfloat16& hi, __nv_bfloat16& lo) {
    hi = __float2bfloat16(f);
    lo = __float2bfloat16(f - __bfloat162float(hi));
}

// ---------------------------------------------------------------------------
// RoPE tables
// ---------------------------------------------------------------------------
__global__ void rope_tables_kernel() {
    int idx = blockIdx.x * blockDim.x + threadIdx.x;
    if (idx >= MM * HALF_D) return;
    int m = idx / HALF_D;
    int i = idx % HALF_D;
    double theta_d = pow(10000.0, -2.0 * ((double)i - 1.0) / (double)DD);
    float ang = (float)m * (float)theta_d;
    g_cos[idx] = cosf(ang);
    g_sin[idx] = sinf(ang);
}

// ---------------------------------------------------------------------------
// fp32 -> 3-segment bf16 split. A-side: [hi,lo,hi]; B-side: [hi,hi,lo]
// ---------------------------------------------------------------------------
template <bool ASIDE>
__global__ void cvt3_kernel(const float* __restrict__ src, __nv_bfloat16* __restrict__ dst,
                            long total, int K) {
    long idx = (long)blockIdx.x * blockDim.x + threadIdx.x;
    if (idx >= total) return;
    long row = idx / K;
    int k = (int)(idx % K);
    __nv_bfloat16 hi, lo;
    split_bf16(src[idx], hi, lo);
    __nv_bfloat16* r = dst + row * (long)(3 * K);
    r[k] = hi;
    r[K + k] = ASIDE ? lo : hi;
    r[2 * K + k] = ASIDE ? hi : lo;
}

// ---------------------------------------------------------------------------
// RoPE rotate fp32 [ROWS,DD] -> 3-segment bf16 split (fused)
// ---------------------------------------------------------------------------
template <bool ASIDE>
__global__ void rope_cvt_kernel(const float* __restrict__ t, __nv_bfloat16* __restrict__ dst) {
    long idx = (long)blockIdx.x * blockDim.x + threadIdx.x;
    if (idx >= (long)ROWS * HALF_D) return;
    int col = (int)(idx % HALF_D);
    long row = idx / HALF_D;
    int m = (int)(row % MM);
    float2 v = reinterpret_cast<const float2*>(t + row * DD)[col];
    float c = g_cos[(size_t)m * HALF_D + col];
    float s = g_sin[(size_t)m * HALF_D + col];
    float re = v.x * c + v.y * s;
    float ro = -v.x * s + v.y * c;
    __nv_bfloat16 he, le, ho, lo;
    split_bf16(re, he, le);
    split_bf16(ro, ho, lo);
    __nv_bfloat16* r = dst + row * (long)K3P;
    int k = 2 * col;
    *reinterpret_cast<__nv_bfloat162*>(r + k)            = __halves2bfloat162(he, ho);
    *reinterpret_cast<__nv_bfloat162*>(r + DD + k)       = ASIDE ? __halves2bfloat162(le, lo)
                                                                 : __halves2bfloat162(he, ho);
    *reinterpret_cast<__nv_bfloat162*>(r + 2 * DD + k)   = ASIDE ? __halves2bfloat162(he, ho)
                                                                 : __halves2bfloat162(le, lo);
}

// ---------------------------------------------------------------------------
// V [b*MM + k][n] -> V3T [b*DD + n][seg*MM + k]  (transpose + split, B-side)
// ---------------------------------------------------------------------------
__global__ void vT_cvt_kernel(const float* __restrict__ V, __nv_bfloat16* __restrict__ V3T) {
    __shared__ float ts[32][33];
    int b = blockIdx.z;
    int n0 = blockIdx.x * 32, k0 = blockIdx.y * 32;
    int tx = threadIdx.x, ty = threadIdx.y;  // 32 x 8
#pragma unroll
    for (int i = 0; i < 4; i++) {
        int k = k0 + ty + i * 8;
        ts[ty + i * 8][tx] = V[((long)(b * MM + k)) * DD + n0 + tx];
    }
    __syncthreads();
#pragma unroll
    for (int i = 0; i < 4; i++) {
        int n = n0 + ty + i * 8;
        float f = ts[tx][ty + i * 8];
        __nv_bfloat16 hi, lo;
        split_bf16(f, hi, lo);
        __nv_bfloat16* r = V3T + ((long)(b * DD + n)) * K3S;
        int k = k0 + tx;
        r[k] = hi;
        r[MM + k] = hi;
        r[2 * MM + k] = lo;
    }
}

// ---------------------------------------------------------------------------
// Row softmax (len MM) fused with A-side split conversion
// ---------------------------------------------------------------------------
__global__ void __launch_bounds__(256) softmax_cvt_kernel(const float* __restrict__ S,
                                                          __nv_bfloat16* __restrict__ S3) {
    __shared__ float red[256];
    long row = blockIdx.x;
    const float4* p = reinterpret_cast<const float4*>(S + row * (long)MM);
    int t = threadIdx.x;
    float4 v0 = p[t];
    float4 v1 = p[t + 256];

    float mx = fmaxf(fmaxf(fmaxf(v0.x, v0.y), fmaxf(v0.z, v0.w)),
                     fmaxf(fmaxf(v1.x, v1.y), fmaxf(v1.z, v1.w)));
    red[t] = mx;
    __syncthreads();
    for (int s = 128; s > 0; s >>= 1) {
        if (t < s) red[t] = fmaxf(red[t], red[t + s]);
        __syncthreads();
    }
    mx = red[0];
    __syncthreads();

    v0.x = expf(v0.x - mx); v0.y = expf(v0.y - mx);
    v0.z = expf(v0.z - mx); v0.w = expf(v0.w - mx);
    v1.x = expf(v1.x - mx); v1.y = expf(v1.y - mx);
    v1.z = expf(v1.z - mx); v1.w = expf(v1.w - mx);

    float sum = (v0.x + v0.y + v0.z + v0.w) + (v1.x + v1.y + v1.z + v1.w);
    red[t] = sum;
    __syncthreads();
    for (int s = 128; s > 0; s >>= 1) {
        if (t < s) red[t] += red[t + s];
        __syncthreads();
    }
    float inv = 1.0f / red[0];
    __syncthreads();

    __nv_bfloat16* r = S3 + row * (long)K3S;
    float f[8] = {v0.x * inv, v0.y * inv, v0.z * inv, v0.w * inv,
                  v1.x * inv, v1.y * inv, v1.z * inv, v1.w * inv};
    int cb[2] = {4 * t, 1024 + 4 * t};
#pragma unroll
    for (int h = 0; h < 2; h++) {
#pragma unroll
        for (int j = 0; j < 4; j += 2) {
            __nv_bfloat16 h0, l0, h1, l1;
            split_bf16(f[h * 4 + j], h0, l0);
            split_bf16(f[h * 4 + j + 1], h1, l1);
            int k = cb[h] + j;
            *reinterpret_cast<__nv_bfloat162*>(r + k)          = __halves2bfloat162(h0, h1);
            *reinterpret_cast<__nv_bfloat162*>(r + MM + k)     = __halves2bfloat162(l0, l1);  // lo (A-side)
            *reinterpret_cast<__nv_bfloat162*>(r + 2 * MM + k) = __halves2bfloat162(h0, h1);
        }
    }
}

// ---------------------------------------------------------------------------
// mma.sync bf16 GEMM (NT, both operands K-major):
//   C[128x128 tile] = alpha * A[row0.., K3] x B[col0.., K3]^T
// BK=64, cp.async double-buffered, XOR-swizzled smem, 8 warps (4M x 2N),
// each warp 32x64 via m16n8k16.
// ---------------------------------------------------------------------------
#define BKC 64                     // K per chunk (bf16 elems)
#define TILE_BYTES (128 * BKC * 2) // 16 KB per operand tile
#define GEMM_SMEM (4 * TILE_BYTES) // A0,B0,A1,B1 = 64 KB

__global__ void __launch_bounds__(256, 2) mma_gemm_kernel(
    const __nv_bfloat16* __restrict__ A, const __nv_bfloat16* __restrict__ B,
    float* __restrict__ C, int K3, int ldc, long sA, long sB, long sC, float alpha)
{
    extern __shared__ char smem[];
    const uint32_t sb = smem_u32(smem);
    const int tid = threadIdx.x;
    const int wid = tid >> 5, lane = tid & 31;
    const int wm = wid & 3;          // warp M index (x32 rows)
    const int wn = wid >> 2;         // warp N index (x64 cols)

    const long row0 = (long)blockIdx.y * 128;
    const long col0 = (long)blockIdx.x * 128;
    const __nv_bfloat16* Abase = A + blockIdx.z * sA + row0 * K3;
    const __nv_bfloat16* Bbase = B + blockIdx.z * sB + col0 * K3;
    float* Cbase = C + blockIdx.z * sC;

    // cp.async load coordinates: 1024 chunks of 16B per operand tile
    const int ldRow = tid >> 3;          // base row (4 iterations of +32... see loop)
    const int ldC = tid & 7;             // 16B chunk within 128B row

    float acc[2][8][4];
#pragma unroll
    for (int i = 0; i < 2; i++)
#pragma unroll
        for (int j = 0; j < 8; j++)
#pragma unroll
            for (int q = 0; q < 4; q++) acc[i][j][q] = 0.0f;

    const int nch = K3 >> 6;

    // ---- tile loader (A and B identical layout) ----
    auto load_tile = [&](int ch, int buf) {
        const long k0 = (long)ch << 6;
        const uint32_t sbA = sb + buf * 2 * TILE_BYTES;
        const uint32_t sbB = sbA + TILE_BYTES;
#pragma unroll
        for (int i = 0; i < 4; i++) {
            int row = ldRow + i * 32;
            int c = ldC;
            uint32_t off = ((uint32_t)row * 8u + (uint32_t)(c ^ (row & 7))) * 16u;
            cpasync16(sbA + off, Abase + (long)row * K3 + k0 + c * 8);
            cpasync16(sbB + off, Bbase + (long)row * K3 + k0 + c * 8);
        }
    };

    load_tile(0, 0);
    cp_commit();

    for (int ch = 0; ch < nch; ch++) {
        if (ch + 1 < nch) {
            load_tile(ch + 1, (ch + 1) & 1);
            cp_commit();
            cp_wait<1>();
        } else {
            cp_wait<0>();
        }
        __syncthreads();

        const uint32_t sbA = sb + (ch & 1) * 2 * TILE_BYTES;
        const uint32_t sbB = sbA + TILE_BYTES;

#pragma unroll
        for (int ks = 0; ks < 4; ks++) {             // 4 k16 steps in BK=64
            uint32_t a[2][4];
            uint32_t b[8][2];
            // A frags: 2 m16 tiles
#pragma unroll
            for (int mt = 0; mt < 2; mt++) {
                int row = wm * 32 + mt * 16 + (lane & 15);
                int c = 2 * ks + (lane >> 4);
                uint32_t addr = sbA + ((uint32_t)row * 8u + (uint32_t)(c ^ (row & 7))) * 16u;
                ldsm4(a[mt], addr);
            }
            // B frags: 4 ldmatrix.x4, each covers two n8 tiles
#pragma unroll
            for (int p = 0; p < 4; p++) {
                int row = wn * 64 + p * 16 + (lane & 15);
                int c = 2 * ks + (lane >> 4);
                uint32_t addr = sbB + ((uint32_t)row * 8u + (uint32_t)(c ^ (row & 7))) * 16u;
                uint32_t r[4];
                ldsm4(r, addr);
                b[2 * p][0] = r[0]; b[2 * p][1] = r[2];
                b[2 * p + 1][0] = r[1]; b[2 * p + 1][1] = r[3];
            }
#pragma unroll
            for (int mt = 0; mt < 2; mt++)
#pragma unroll
                for (int nt = 0; nt < 8; nt++)
                    mma16816(acc[mt][nt], a[mt], b[nt]);
        }
        __syncthreads();
    }

    // ---- epilogue ----
    const int g = lane >> 2, tg = lane & 3;
#pragma unroll
    for (int mt = 0; mt < 2; mt++) {
        long r0 = row0 + wm * 32 + mt * 16 + g;
#pragma unroll
        for (int nt = 0; nt < 8; nt++) {
            long cc = col0 + wn * 64 + nt * 8 + tg * 2;
            float2 v0 = make_float2(alpha * acc[mt][nt][0], alpha * acc[mt][nt][1]);
            float2 v1 = make_float2(alpha * acc[mt][nt][2], alpha * acc[mt][nt][3]);
            *reinterpret_cast<float2*>(Cbase + r0 * ldc + cc) = v0;
            *reinterpret_cast<float2*>(Cbase + (r0 + 8) * ldc + cc) = v1;
        }
    }
}

// ---------------------------------------------------------------------------
// Launch
// ---------------------------------------------------------------------------
extern "C" void kernel_launch(void* const* d_in, const int* in_sizes, int n_in,
                              void* d_out, int out_size) {
    (void)in_sizes; (void)n_in; (void)out_size;
    const float* x  = (const float*)d_in[0];
    const float* wq = (const float*)d_in[1];
    const float* wk = (const float*)d_in[2];
    const float* wv = (const float*)d_in[3];
    float* out = (float*)d_out;

    __nv_bfloat16 *x3, *w3q, *w3k, *w3v, *Q3, *K3, *V3T, *S3;
    float *Qf, *Kf, *Vf, *Sf;
    cudaGetSymbolAddress((void**)&x3, g_x3);
    cudaGetSymbolAddress((void**)&w3q, g_w3q);
    cudaGetSymbolAddress((void**)&w3k, g_w3k);
    cudaGetSymbolAddress((void**)&w3v, g_w3v);
    cudaGetSymbolAddress((void**)&Qf, g_Qf);
    cudaGetSymbolAddress((void**)&Kf, g_Kf);
    cudaGetSymbolAddress((void**)&Vf, g_Vf);
    cudaGetSymbolAddress((void**)&Q3, g_Q3);
    cudaGetSymbolAddress((void**)&K3, g_K3);
    cudaGetSymbolAddress((void**)&V3T, g_V3T);
    cudaGetSymbolAddress((void**)&Sf, g_Sf);
    cudaGetSymbolAddress((void**)&S3, g_S3);

    cudaFuncSetAttribute(mma_gemm_kernel, cudaFuncAttributeMaxDynamicSharedMemorySize, GEMM_SMEM);

    // 1. RoPE tables + input conversions
    rope_tables_kernel<<<(MM * HALF_D + 255) / 256, 256>>>();
    cvt3_kernel<true><<<(int)(((long)ROWS * DD + 255) / 256), 256>>>(x, x3, (long)ROWS * DD, DD);
    cvt3_kernel<false><<<(DD * DD + 255) / 256, 256>>>(wq, w3q, (long)DD * DD, DD);
    cvt3_kernel<false><<<(DD * DD + 255) / 256, 256>>>(wk, w3k, (long)DD * DD, DD);
    cvt3_kernel<false><<<(DD * DD + 255) / 256, 256>>>(wv, w3v, (long)DD * DD, DD);

    // 2. Projections (tensor cores): Q/K/V fp32 = x @ W^T
    dim3 gProj(DD / 128, ROWS / 128, 1);
    mma_gemm_kernel<<<gProj, 256, GEMM_SMEM>>>(x3, w3q, Qf, K3P, DD, 0, 0, 0, 1.0f);
    mma_gemm_kernel<<<gProj, 256, GEMM_SMEM>>>(x3, w3k, Kf, K3P, DD, 0, 0, 0, 1.0f);
    mma_gemm_kernel<<<gProj, 256, GEMM_SMEM>>>(x3, w3v, Vf, K3P, DD, 0, 0, 0, 1.0f);

    // 3. RoPE + split (Q: A-side, K: B-side), V transpose + split
    long pairs = (long)ROWS * HALF_D;
    rope_cvt_kernel<true><<<(int)((pairs + 255) / 256), 256>>>(Qf, Q3);
    rope_cvt_kernel<false><<<(int)((pairs + 255) / 256), 256>>>(Kf, K3);
    dim3 gV(DD / 32, MM / 32, BB);
    vT_cvt_kernel<<<gV, dim3(32, 8)>>>(Vf, V3T);

    // 4. scores = Qr @ Kr^T / 32
    dim3 gScore(MM / 128, MM / 128, BB);
    mma_gemm_kernel<<<gScore, 256, GEMM_SMEM>>>(Q3, K3, Sf, K3P, MM,
                                                (long)MM * K3P, (long)MM * K3P,
                                                (long)MM * MM, 0.03125f);

    // 5. softmax + split
    softmax_cvt_kernel<<<BB * MM, 256>>>(Sf, S3);

    // 6. out = attn @ V
    dim3 gOut(DD / 128, MM / 128, BB);
    mma_gemm_kernel<<<gOut, 256, GEMM_SMEM>>>(S3, V3T, out, K3S, DD,
                                              (long)MM * K3S, (long)DD * K3S,
                                              (long)MM * DD, 1.0f);
}

// round 4
// speedup vs baseline: 2.7199x; 1.0076x over previous
#include <cuda_runtime.h>
#include <cuda_bf16.h>
#include <math.h>
#include <stdint.h>

// Problem dims (fixed)
#define BB 8
#define MM 2048
#define DD 1024
#define HALF_D 512
#define ROWS 16384           // BB*MM
#define K3P 3072             // 3*DD  (split-K for K=1024 GEMMs)
#define K3S 6144             // 3*MM  (split-K for PV GEMM, K=2048)

// ---------------------------------------------------------------------------
// Device-global scratch (allocation-free, graph-capture safe)
// ---------------------------------------------------------------------------
__device__ __nv_bfloat16 g_x3[(size_t)ROWS * K3P];       // x  split, A-side
__device__ __nv_bfloat16 g_w3[(size_t)(3 * DD) * K3P];   // [wq;wk;wv] split, B-side
__device__ float g_Vf[(size_t)ROWS * DD];
__device__ __nv_bfloat16 g_Q3[(size_t)ROWS * K3P];       // rotated Q split, A-side
__device__ __nv_bfloat16 g_K3[(size_t)ROWS * K3P];       // rotated K split, B-side
__device__ __nv_bfloat16 g_V3T[(size_t)BB * DD * K3S];   // V^T split, B-side
__device__ float g_Sf[(size_t)BB * MM * MM];             // scores fp32
__device__ __nv_bfloat16 g_S3[(size_t)BB * MM * K3S];    // attn split, A-side
__device__ float g_cos[(size_t)MM * HALF_D];
__device__ float g_sin[(size_t)MM * HALF_D];

// ---------------------------------------------------------------------------
// PTX helpers (base-ISA: mma.sync / ldmatrix / cp.async)
// ---------------------------------------------------------------------------
__device__ __forceinline__ uint32_t smem_u32(const void* p) {
    uint32_t a;
    asm("{ .reg .u64 t; cvta.to.shared.u64 t, %1; cvt.u32.u64 %0, t; }" : "=r"(a) : "l"(p));
    return a;
}
__device__ __forceinline__ void mma16816(float* d, const uint32_t* a, const uint32_t* b) {
    asm volatile(
        "mma.sync.aligned.m16n8k16.row.col.f32.bf16.bf16.f32 "
        "{%0,%1,%2,%3}, {%4,%5,%6,%7}, {%8,%9}, {%0,%1,%2,%3};"
        : "+f"(d[0]), "+f"(d[1]), "+f"(d[2]), "+f"(d[3])
        : "r"(a[0]), "r"(a[1]), "r"(a[2]), "r"(a[3]), "r"(b[0]), "r"(b[1]));
}
__device__ __forceinline__ void ldsm4(uint32_t* r, uint32_t addr) {
    asm volatile("ldmatrix.sync.aligned.m8n8.x4.shared.b16 {%0,%1,%2,%3}, [%4];"
                 : "=r"(r[0]), "=r"(r[1]), "=r"(r[2]), "=r"(r[3]) : "r"(addr));
}
__device__ __forceinline__ void cpasync16(uint32_t dst, const void* src) {
    asm volatile("cp.async.cg.shared.global [%0], [%1], 16;" :: "r"(dst), "l"(src));
}
__device__ __forceinline__ void cp_commit() {
    asm volatile("cp.async.commit_group;" ::: "memory");
}
template <int N>
__device__ __forceinline__ void cp_wait() {
    asm volatile("cp.async.wait_group %0;" :: "n"(N) : "memory");
}

// ---------------------------------------------------------------------------
// bf16 split helpers
// ---------------------------------------------------------------------------
__device__ __forceinline__ void split_bf16(float f, __nv_bfloat16& hi, __nv_bfloat16& lo) {
    hi = __float2bfloat16(f);
    lo = __float2bfloat16(f - __bfloat162float(hi));
}

// ---------------------------------------------------------------------------
// RoPE tables
// ---------------------------------------------------------------------------
__global__ void rope_tables_kernel() {
    int idx = blockIdx.x * blockDim.x + threadIdx.x;
    if (idx >= MM * HALF_D) return;
    int m = idx / HALF_D;
    int i = idx % HALF_D;
    double theta_d = pow(10000.0, -2.0 * ((double)i - 1.0) / (double)DD);
    float ang = (float)m * (float)theta_d;
    g_cos[idx] = cosf(ang);
    g_sin[idx] = sinf(ang);
}

// ---------------------------------------------------------------------------
// fp32 -> 3-segment bf16 split. A-side: [hi,lo,hi]; B-side: [hi,hi,lo]
// ---------------------------------------------------------------------------
template <bool ASIDE>
__global__ void cvt3_kernel(const float* __restrict__ src, __nv_bfloat16* __restrict__ dst,
                            long total, int K) {
    long idx = (long)blockIdx.x * blockDim.x + threadIdx.x;
    if (idx >= total) return;
    long row = idx / K;
    int k = (int)(idx % K);
    __nv_bfloat16 hi, lo;
    split_bf16(src[idx], hi, lo);
    __nv_bfloat16* r = dst + row * (long)(3 * K);
    r[k] = hi;
    r[K + k] = ASIDE ? lo : hi;
    r[2 * K + k] = ASIDE ? hi : lo;
}

// ---------------------------------------------------------------------------
// V [b*MM + k][n] -> V3T [b*DD + n][seg*MM + k]  (transpose + split, B-side)
// ---------------------------------------------------------------------------
__global__ void vT_cvt_kernel(const float* __restrict__ V, __nv_bfloat16* __restrict__ V3T) {
    __shared__ float ts[32][33];
    int b = blockIdx.z;
    int n0 = blockIdx.x * 32, k0 = blockIdx.y * 32;
    int tx = threadIdx.x, ty = threadIdx.y;  // 32 x 8
#pragma unroll
    for (int i = 0; i < 4; i++) {
        int k = k0 + ty + i * 8;
        ts[ty + i * 8][tx] = V[((long)(b * MM + k)) * DD + n0 + tx];
    }
    __syncthreads();
#pragma unroll
    for (int i = 0; i < 4; i++) {
        int n = n0 + ty + i * 8;
        float f = ts[tx][ty + i * 8];
        __nv_bfloat16 hi, lo;
        split_bf16(f, hi, lo);
        __nv_bfloat16* r = V3T + ((long)(b * DD + n)) * K3S;
        int k = k0 + tx;
        r[k] = hi;
        r[MM + k] = hi;
        r[2 * MM + k] = lo;
    }
}

// ---------------------------------------------------------------------------
// Row softmax (len MM) fused with A-side split conversion
// ---------------------------------------------------------------------------
__global__ void __launch_bounds__(256) softmax_cvt_kernel(const float* __restrict__ S,
                                                          __nv_bfloat16* __restrict__ S3) {
    __shared__ float red[256];
    long row = blockIdx.x;
    const float4* p = reinterpret_cast<const float4*>(S + row * (long)MM);
    int t = threadIdx.x;
    float4 v0 = p[t];
    float4 v1 = p[t + 256];

    float mx = fmaxf(fmaxf(fmaxf(v0.x, v0.y), fmaxf(v0.z, v0.w)),
                     fmaxf(fmaxf(v1.x, v1.y), fmaxf(v1.z, v1.w)));
    red[t] = mx;
    __syncthreads();
    for (int s = 128; s > 0; s >>= 1) {
        if (t < s) red[t] = fmaxf(red[t], red[t + s]);
        __syncthreads();
    }
    mx = red[0];
    __syncthreads();

    v0.x = expf(v0.x - mx); v0.y = expf(v0.y - mx);
    v0.z = expf(v0.z - mx); v0.w = expf(v0.w - mx);
    v1.x = expf(v1.x - mx); v1.y = expf(v1.y - mx);
    v1.z = expf(v1.z - mx); v1.w = expf(v1.w - mx);

    float sum = (v0.x + v0.y + v0.z + v0.w) + (v1.x + v1.y + v1.z + v1.w);
    red[t] = sum;
    __syncthreads();
    for (int s = 128; s > 0; s >>= 1) {
        if (t < s) red[t] += red[t + s];
        __syncthreads();
    }
    float inv = 1.0f / red[0];
    __syncthreads();

    __nv_bfloat16* r = S3 + row * (long)K3S;
    float f[8] = {v0.x * inv, v0.y * inv, v0.z * inv, v0.w * inv,
                  v1.x * inv, v1.y * inv, v1.z * inv, v1.w * inv};
    int cb[2] = {4 * t, 1024 + 4 * t};
#pragma unroll
    for (int h = 0; h < 2; h++) {
#pragma unroll
        for (int j = 0; j < 4; j += 2) {
            __nv_bfloat16 h0, l0, h1, l1;
            split_bf16(f[h * 4 + j], h0, l0);
            split_bf16(f[h * 4 + j + 1], h1, l1);
            int k = cb[h] + j;
            *reinterpret_cast<__nv_bfloat162*>(r + k)          = __halves2bfloat162(h0, h1);
            *reinterpret_cast<__nv_bfloat162*>(r + MM + k)     = __halves2bfloat162(l0, l1);  // lo (A-side)
            *reinterpret_cast<__nv_bfloat162*>(r + 2 * MM + k) = __halves2bfloat162(h0, h1);
        }
    }
}

// ---------------------------------------------------------------------------
// mma.sync bf16 GEMM (NT, both operands K-major), 128x128 CTA tile, BK=64,
// 3-stage cp.async pipeline, XOR-swizzled smem, 8 warps (4M x 2N).
//   EPI=0: C[m,n] = alpha * A x B^T   (fp32 store)
//   EPI=1: merged QKV projection epilogue: cols [0,1024) -> RoPE+split -> g_Q3,
//          cols [1024,2048) -> RoPE+split -> g_K3, cols [2048,3072) -> fp32 g_Vf
// ---------------------------------------------------------------------------
#define BKC 64                     // K per chunk (bf16 elems)
#define TILE_BYTES (128 * BKC * 2) // 16 KB per operand tile
#define GEMM_SMEM (6 * TILE_BYTES) // 3 stages x (A+B) = 96 KB

template <int EPI>
__global__ void __launch_bounds__(256, 2) mma_gemm_kernel(
    const __nv_bfloat16* __restrict__ A, const __nv_bfloat16* __restrict__ B,
    float* __restrict__ C, int K3, int ldc, long sA, long sB, long sC, float alpha)
{
    extern __shared__ char smem[];
    const uint32_t sb = smem_u32(smem);
    const int tid = threadIdx.x;
    const int wid = tid >> 5, lane = tid & 31;
    const int wm = wid & 3;          // warp M index (x32 rows)
    const int wn = wid >> 2;         // warp N index (x64 cols)

    const long row0 = (long)blockIdx.y * 128;
    const long col0 = (long)blockIdx.x * 128;
    const __nv_bfloat16* Abase = A + blockIdx.z * sA + row0 * K3;
    const __nv_bfloat16* Bbase = B + blockIdx.z * sB + col0 * K3;
    float* Cbase = C + blockIdx.z * sC;

    const int ldRow = tid >> 3;      // rows 0..31 (+32*i)
    const int ldC = tid & 7;         // 16B chunk within 128B row

    float acc[2][8][4];
#pragma unroll
    for (int i = 0; i < 2; i++)
#pragma unroll
        for (int j = 0; j < 8; j++)
#pragma unroll
            for (int q = 0; q < 4; q++) acc[i][j][q] = 0.0f;

    const int nch = K3 >> 6;

    auto load_tile = [&](int ch, int buf) {
        const long k0 = (long)ch << 6;
        const uint32_t sbA = sb + buf * 2 * TILE_BYTES;
        const uint32_t sbB = sbA + TILE_BYTES;
#pragma unroll
        for (int i = 0; i < 4; i++) {
            int row = ldRow + i * 32;
            int c = ldC;
            uint32_t off = ((uint32_t)row * 8u + (uint32_t)(c ^ (row & 7))) * 16u;
            cpasync16(sbA + off, Abase + (long)row * K3 + k0 + c * 8);
            cpasync16(sbB + off, Bbase + (long)row * K3 + k0 + c * 8);
        }
    };

    load_tile(0, 0);
    cp_commit();
    load_tile(1, 1);
    cp_commit();

    for (int ch = 0; ch < nch; ch++) {
        if (ch + 2 < nch) {
            load_tile(ch + 2, (ch + 2) % 3);
            cp_commit();
            cp_wait<2>();
        } else if (ch + 1 < nch) {
            cp_wait<1>();
        } else {
            cp_wait<0>();
        }
        __syncthreads();

        const uint32_t sbA = sb + (ch % 3) * 2 * TILE_BYTES;
        const uint32_t sbB = sbA + TILE_BYTES;

#pragma unroll
        for (int ks = 0; ks < 4; ks++) {             // 4 k16 steps in BK=64
            uint32_t a[2][4];
            uint32_t b[8][2];
#pragma unroll
            for (int mt = 0; mt < 2; mt++) {
                int row = wm * 32 + mt * 16 + (lane & 15);
                int c = 2 * ks + (lane >> 4);
                uint32_t addr = sbA + ((uint32_t)row * 8u + (uint32_t)(c ^ (row & 7))) * 16u;
                ldsm4(a[mt], addr);
            }
#pragma unroll
            for (int p = 0; p < 4; p++) {
                int row = wn * 64 + p * 16 + (lane & 15);
                int c = 2 * ks + (lane >> 4);
                uint32_t addr = sbB + ((uint32_t)row * 8u + (uint32_t)(c ^ (row & 7))) * 16u;
                uint32_t r[4];
                ldsm4(r, addr);
                b[2 * p][0] = r[0]; b[2 * p][1] = r[2];
                b[2 * p + 1][0] = r[1]; b[2 * p + 1][1] = r[3];
            }
#pragma unroll
            for (int mt = 0; mt < 2; mt++)
#pragma unroll
                for (int nt = 0; nt < 8; nt++)
                    mma16816(acc[mt][nt], a[mt], b[nt]);
        }
        __syncthreads();
    }

    // ---- epilogue ----
    const int g = lane >> 2, tg = lane & 3;
    if (EPI == 0) {
#pragma unroll
        for (int mt = 0; mt < 2; mt++) {
            long r0 = row0 + wm * 32 + mt * 16 + g;
#pragma unroll
            for (int nt = 0; nt < 8; nt++) {
                long cc = col0 + wn * 64 + nt * 8 + tg * 2;
                float2 v0 = make_float2(alpha * acc[mt][nt][0], alpha * acc[mt][nt][1]);
                float2 v1 = make_float2(alpha * acc[mt][nt][2], alpha * acc[mt][nt][3]);
                *reinterpret_cast<float2*>(Cbase + r0 * ldc + cc) = v0;
                *reinterpret_cast<float2*>(Cbase + (r0 + 8) * ldc + cc) = v1;
            }
        }
    } else {
        // merged QKV epilogue. n in [0,3072): Q | K | V
        const int nbase = (int)col0 + wn * 64 + tg * 2;
#pragma unroll
        for (int mt = 0; mt < 2; mt++) {
            long r0 = row0 + wm * 32 + mt * 16 + g;   // global row (+8 for second half)
#pragma unroll
            for (int nt = 0; nt < 8; nt++) {
                int n = nbase + nt * 8;
                if (n < 2048) {
                    // RoPE + 3-seg split
                    int k = n & 1023;                 // col within Q or K block
                    int pidx = k >> 1;
#pragma unroll
                    for (int h = 0; h < 2; h++) {
                        long r = r0 + h * 8;
                        int m = (int)(r & (MM - 1));
                        float c = g_cos[(size_t)m * HALF_D + pidx];
                        float s = g_sin[(size_t)m * HALF_D + pidx];
                        float e = acc[mt][nt][2 * h], o = acc[mt][nt][2 * h + 1];
                        float re = e * c + o * s;
                        float ro = -e * s + o * c;
                        __nv_bfloat16 he, le, ho, lo;
                        split_bf16(re, he, le);
                        split_bf16(ro, ho, lo);
                        __nv_bfloat16* dst = (n < 1024 ? g_Q3 : g_K3) + r * (long)K3P + k;
                        __nv_bfloat162 hi2 = __halves2bfloat162(he, ho);
                        __nv_bfloat162 lo2 = __halves2bfloat162(le, lo);
                        // Q (A-side): [hi,lo,hi]   K (B-side): [hi,hi,lo]
                        *reinterpret_cast<__nv_bfloat162*>(dst) = hi2;
                        *reinterpret_cast<__nv_bfloat162*>(dst + DD) = (n < 1024) ? lo2 : hi2;
                        *reinterpret_cast<__nv_bfloat162*>(dst + 2 * DD) = (n < 1024) ? hi2 : lo2;
                    }
                } else {
                    int k = n - 2048;
                    float2 v0 = make_float2(acc[mt][nt][0], acc[mt][nt][1]);
                    float2 v1 = make_float2(acc[mt][nt][2], acc[mt][nt][3]);
                    *reinterpret_cast<float2*>(g_Vf + r0 * DD + k) = v0;
                    *reinterpret_cast<float2*>(g_Vf + (r0 + 8) * DD + k) = v1;
                }
            }
        }
    }
}

// ---------------------------------------------------------------------------
// Launch
// ---------------------------------------------------------------------------
extern "C" void kernel_launch(void* const* d_in, const int* in_sizes, int n_in,
                              void* d_out, int out_size) {
    (void)in_sizes; (void)n_in; (void)out_size;
    const float* x  = (const float*)d_in[0];
    const float* wq = (const float*)d_in[1];
    const float* wk = (const float*)d_in[2];
    const float* wv = (const float*)d_in[3];
    float* out = (float*)d_out;

    __nv_bfloat16 *x3, *w3, *Q3, *K3, *V3T, *S3;
    float *Vf, *Sf;
    cudaGetSymbolAddress((void**)&x3, g_x3);
    cudaGetSymbolAddress((void**)&w3, g_w3);
    cudaGetSymbolAddress((void**)&Vf, g_Vf);
    cudaGetSymbolAddress((void**)&Q3, g_Q3);
    cudaGetSymbolAddress((void**)&K3, g_K3);
    cudaGetSymbolAddress((void**)&V3T, g_V3T);
    cudaGetSymbolAddress((void**)&Sf, g_Sf);
    cudaGetSymbolAddress((void**)&S3, g_S3);

    cudaFuncSetAttribute(mma_gemm_kernel<0>, cudaFuncAttributeMaxDynamicSharedMemorySize, GEMM_SMEM);
    cudaFuncSetAttribute(mma_gemm_kernel<1>, cudaFuncAttributeMaxDynamicSharedMemorySize, GEMM_SMEM);

    // 1. RoPE tables + input conversions
    rope_tables_kernel<<<(MM * HALF_D + 255) / 256, 256>>>();
    cvt3_kernel<true><<<(int)(((long)ROWS * DD + 255) / 256), 256>>>(x, x3, (long)ROWS * DD, DD);
    cvt3_kernel<false><<<(DD * DD + 255) / 256, 256>>>(wq, w3, (long)DD * DD, DD);
    cvt3_kernel<false><<<(DD * DD + 255) / 256, 256>>>(wk, w3 + (size_t)DD * K3P, (long)DD * DD, DD);
    cvt3_kernel<false><<<(DD * DD + 255) / 256, 256>>>(wv, w3 + (size_t)2 * DD * K3P, (long)DD * DD, DD);

    // 2. Merged QKV projection with fused RoPE/split epilogue
    dim3 gProj(3 * DD / 128, ROWS / 128, 1);
    mma_gemm_kernel<1><<<gProj, 256, GEMM_SMEM>>>(x3, w3, nullptr, K3P, 0, 0, 0, 0, 1.0f);

    // 3. V transpose + split
    dim3 gV(DD / 32, MM / 32, BB);
    vT_cvt_kernel<<<gV, dim3(32, 8)>>>(Vf, V3T);

    // 4. scores = Qr @ Kr^T / 32
    dim3 gScore(MM / 128, MM / 128, BB);
    mma_gemm_kernel<0><<<gScore, 256, GEMM_SMEM>>>(Q3, K3, Sf, K3P, MM,
                                                   (long)MM * K3P, (long)MM * K3P,
                                                   (long)MM * MM, 0.03125f);

    // 5. softmax + split
    softmax_cvt_kernel<<<BB * MM, 256>>>(Sf, S3);

    // 6. out = attn @ V
    dim3 gOut(DD / 128, MM / 128, BB);
    mma_gemm_kernel<0><<<gOut, 256, GEMM_SMEM>>>(S3, V3T, out, K3S, DD,
                                                 (long)MM * K3S, (long)DD * K3S,
                                                 (long)MM * DD, 1.0f);
}